// round 2
// baseline (speedup 1.0000x reference)
#include <cuda_runtime.h>

// BackgroundStd2D: masked per-(b,c) std over HW.
// bf: (4,256,256,256) f32, mask: (4,1,256,256) f32, min_std: (1,256,1,1) f32
// out: (4,256) f32 = max(std_bc, 1e-6 + min_std[c])
//
// Two-stage: stage 1 compresses the (batch-shared, channel-independent) mask
// into a 32 KB bitmask + per-block keep-counts, so stage 2 never re-reads the
// 1 MB fp32 mask 256x per batch (kills 256 MB of L2 traffic).

#define B 4
#define C 256
#define HW 65536                 // 256*256
#define WORDS_PER_BATCH 2048     // HW/32
#define BLKS1_PER_BATCH 32       // stage-1 blocks per batch
#define GRID1 (B * BLKS1_PER_BATCH)

__device__ unsigned int g_bits[B * WORDS_PER_BATCH];  // 32 KB
__device__ int g_partial[GRID1];                      // per-block popcounts

// ---------------- Stage 1: mask -> bitmask + counts ----------------
__global__ __launch_bounds__(256)
void bgstd_bits(const float* __restrict__ mask)
{
    const int b   = blockIdx.x >> 5;        // /BLKS1_PER_BATCH
    const int blk = blockIdx.x & 31;
    const float* __restrict__ m = mask + (size_t)b * HW + blk * 2048;
    unsigned int* __restrict__ gb = g_bits + b * WORDS_PER_BATCH + blk * 64;

    const int tid = threadIdx.x;
    const int lid = tid & 31;
    const int wid = tid >> 5;

    int cnt = 0;
    #pragma unroll
    for (int j = 0; j < 8; j++) {
        int p = j * 256 + tid;              // contiguous within warp
        float mv = m[p];
        unsigned bal = __ballot_sync(0xFFFFFFFFu, mv <= 0.5f);
        if (lid == 0) {
            gb[p >> 5] = bal;
            cnt += __popc(bal);
        }
    }

    __shared__ int sm_cnt[8];
    if (lid == 0) sm_cnt[wid] = cnt;
    __syncthreads();
    if (tid == 0) {
        int tot = 0;
        #pragma unroll
        for (int w = 0; w < 8; w++) tot += sm_cnt[w];
        g_partial[blockIdx.x] = tot;
    }
}

// ---------------- Stage 2: per-(b,c) masked sum / sumsq ----------------
__global__ __launch_bounds__(256, 8)
void bgstd_main(const float* __restrict__ bf,
                const float* __restrict__ min_std,
                float* __restrict__ out)
{
    __shared__ unsigned int sbits[WORDS_PER_BATCH];   // 8 KB

    const int bc = blockIdx.x;        // 0..1023
    const int b  = bc >> 8;
    const int c  = bc & (C - 1);
    const int tid = threadIdx.x;

    // stage bitmask into smem (8 KB, read once per block)
    {
        const unsigned int* __restrict__ gb = g_bits + b * WORDS_PER_BATCH;
        #pragma unroll
        for (int i = tid; i < WORDS_PER_BATCH; i += 256) sbits[i] = gb[i];
    }
    __syncthreads();

    const float4* __restrict__ bf4 = reinterpret_cast<const float4*>(bf + (size_t)bc * HW);

    const int shift = (tid & 7) * 4;     // nibble position, constant per thread
    const int wbase = tid >> 3;          // word within 32-word stripe

    float s0 = 0.0f, s1 = 0.0f, q0 = 0.0f, q1 = 0.0f;

    #pragma unroll 8
    for (int j = 0; j < HW / 4 / 256; j++) {          // 64 iters
        int i = j * 256 + tid;
        float4 v = __ldcs(&bf4[i]);                   // streaming, no reuse
        unsigned nib = (sbits[j * 32 + wbase] >> shift) & 0xFu;

        float t0 = (nib & 1u) ? v.x : 0.0f;
        float t1 = (nib & 2u) ? v.y : 0.0f;
        float t2 = (nib & 4u) ? v.z : 0.0f;
        float t3 = (nib & 8u) ? v.w : 0.0f;

        s0 += t0; q0 = fmaf(t0, t0, q0);
        s1 += t1; q1 = fmaf(t1, t1, q1);
        s0 += t2; q0 = fmaf(t2, t2, q0);
        s1 += t3; q1 = fmaf(t3, t3, q1);
    }

    float s  = s0 + s1;
    float sq = q0 + q1;

    // warp reduce
    #pragma unroll
    for (int off = 16; off > 0; off >>= 1) {
        s  += __shfl_down_sync(0xFFFFFFFFu, s,  off);
        sq += __shfl_down_sync(0xFFFFFFFFu, sq, off);
    }

    __shared__ float sm_s[8], sm_q[8];
    const int wid = tid >> 5;
    const int lid = tid & 31;
    if (lid == 0) { sm_s[wid] = s; sm_q[wid] = sq; }
    __syncthreads();

    if (tid == 0) {
        s = 0.0f; sq = 0.0f;
        #pragma unroll
        for (int w = 0; w < 8; w++) { s += sm_s[w]; sq += sm_q[w]; }

        // n for this batch: sum of 32 stage-1 partials (deterministic int sum)
        int ni = 0;
        #pragma unroll
        for (int k = 0; k < BLKS1_PER_BATCH; k++)
            ni += g_partial[b * BLKS1_PER_BATCH + k];
        float n = (float)ni;

        float var = (sq - s * s / n) / (n - 1.0f);
        float sd = sqrtf(var);
        float thresh = 1e-6f + min_std[c];   // MIN_STD_VAL/10 + min_std
        out[bc] = fmaxf(sd, thresh);
    }
}

extern "C" void kernel_launch(void* const* d_in, const int* in_sizes, int n_in,
                              void* d_out, int out_size)
{
    const float* bf      = (const float*)d_in[0];
    const float* mask    = (const float*)d_in[1];
    const float* min_std = (const float*)d_in[2];
    float* out = (float*)d_out;

    bgstd_bits<<<GRID1, 256>>>(mask);
    bgstd_main<<<B * C, 256>>>(bf, min_std, out);
}